// round 8
// baseline (speedup 1.0000x reference)
#include <cuda_runtime.h>
#include <cstdint>

// Problem constants
#define NLAT 181
#define NLON 360
#define CIN  128
#define COUT 128
#define KS   3
#define BSZ  2
#define CHW  (NLAT * NLON)     // 65160
#define CK   (CIN * KS)        // 384
#define PT   32                // gather p-tile
#define NPT  12
#define MTOT  (BSZ * CHW)      // 130320
#define MTILE 128
#define MBLK  ((MTOT + MTILE - 1) / MTILE)   // 1019
#define MPADL (MBLK * MTILE)                 // 130432
#define WSLOT 4096
#define RSLOT 512
#define KCH   32               // GEMM K-chunk
#define NCH   (CK / KCH)       // 12
#define SROW  36               // padded smem row (words), conflict-free ldmatrix

// Scratch (device globals — allocation-free; zero-init so padded z rows are 0)
__device__ float  g_xt[(size_t)BSZ * CHW * CIN];   // x transposed: [b][h*w][c]
__device__ float4 g_rw[NLAT * WSLOT];              // run weights {w0,w1,w2,0}
__device__ int4   g_runs[NLAT * RSLOT];            // {la, lo0, cnt_padded, wabs}
__device__ int    g_rcnt[NLAT];
__device__ float  g_z[(size_t)MPADL * CK];         // z M-major [m][ck], tf32-rounded
__device__ float  g_wtf[COUT * CK];                // W [f][ck], tf32-rounded

// ---------------- helpers ----------------
__device__ __forceinline__ void fma2(unsigned long long& d,
                                     unsigned long long a,
                                     unsigned long long b) {
    asm("fma.rn.f32x2 %0, %1, %2, %0;" : "+l"(d) : "l"(a), "l"(b));
}
__device__ __forceinline__ unsigned long long pack2(float x, float y) {
    unsigned long long r;
    asm("mov.b64 %0, {%1, %2};" : "=l"(r) : "f"(x), "f"(y));
    return r;
}
union F4U { float4 f; unsigned long long u[2]; };
union U2F { unsigned long long u; float2 f; };

__device__ __forceinline__ float tf32r(float x) {
    uint32_t r;
    asm("cvt.rn.tf32.f32 %0, %1;" : "=r"(r) : "f"(x));
    return __uint_as_float(r);
}
__device__ __forceinline__ uint32_t smem_u32(const void* p) {
    uint32_t a;
    asm("{ .reg .u64 t; cvta.to.shared.u64 t, %1; cvt.u32.u64 %0, t; }"
        : "=r"(a) : "l"(p));
    return a;
}
__device__ __forceinline__ void cpasync16(uint32_t s, const void* g) {
    asm volatile("cp.async.cg.shared.global [%0], [%1], 16;" :: "r"(s), "l"(g));
}
__device__ __forceinline__ void cp_commit() {
    asm volatile("cp.async.commit_group;" ::: "memory");
}
template <int N>
__device__ __forceinline__ void cp_wait() {
    asm volatile("cp.async.wait_group %0;" :: "n"(N) : "memory");
}
__device__ __forceinline__ void mma_tf32(float* d, const uint32_t* a,
                                         uint32_t b0, uint32_t b1) {
    asm volatile(
        "mma.sync.aligned.m16n8k8.row.col.f32.tf32.tf32.f32 "
        "{%0,%1,%2,%3}, {%4,%5,%6,%7}, {%8,%9}, {%0,%1,%2,%3};"
        : "+f"(d[0]), "+f"(d[1]), "+f"(d[2]), "+f"(d[3])
        : "r"(a[0]), "r"(a[1]), "r"(a[2]), "r"(a[3]), "r"(b0), "r"(b1));
}
__device__ __forceinline__ void ldsm_x4(uint32_t& r0, uint32_t& r1,
                                        uint32_t& r2, uint32_t& r3, uint32_t addr) {
    asm volatile("ldmatrix.sync.aligned.m8n8.x4.shared.b16 {%0,%1,%2,%3}, [%4];"
                 : "=r"(r0), "=r"(r1), "=r"(r2), "=r"(r3) : "r"(addr));
}

// ---------------------------------------------------------------------------
// Transpose x[b][c][hw] -> g_xt[b][hw][c]
// ---------------------------------------------------------------------------
__global__ void transpose_kernel(const float* __restrict__ x) {
    __shared__ float tile[32][33];
    const int hw0 = blockIdx.x * 32;
    const int c0  = blockIdx.y * 32;
    const int b   = blockIdx.z;
    const int tx = threadIdx.x, ty = threadIdx.y;
    #pragma unroll
    for (int i = 0; i < 4; i++) {
        int c  = c0 + ty + i * 8;
        int hw = hw0 + tx;
        if (hw < CHW)
            tile[ty + i * 8][tx] = x[((size_t)b * CIN + c) * CHW + hw];
    }
    __syncthreads();
    #pragma unroll
    for (int i = 0; i < 4; i++) {
        int hw = hw0 + ty + i * 8;
        int c  = c0 + tx;
        if (hw < CHW)
            g_xt[((size_t)b * CHW + hw) * CIN + c] = tile[tx][ty + i * 8];
    }
}

// W[f][ck] -> tf32-rounded copy
__global__ void wconv_kernel(const float* __restrict__ w) {
    int i = blockIdx.x * 256 + threadIdx.x;
    if (i < COUT * CK) g_wtf[i] = tf32r(w[i]);
}

// ---------------------------------------------------------------------------
// Merge: warp per t. Emits per-(t,la) runs of consecutive lons with
// branch-free weight triples, zero-padded to multiples of 4 entries.
// ---------------------------------------------------------------------------
__global__ void merge_kernel(const int* __restrict__ seg,
                             const int* __restrict__ lat,
                             const int* __restrict__ lon,
                             const float* __restrict__ vals,
                             const float* __restrict__ qw,
                             int nnz) {
    const int t    = (blockIdx.x * blockDim.x + threadIdx.x) >> 5;
    const int lane = threadIdx.x & 31;
    if (t >= NLAT) return;

    int sb[4];
    #pragma unroll
    for (int k = 0; k < 4; k++) {
        const int j = t * KS + k;
        int lo = 0, hi = nnz;
        while (lo < hi) {
            int m = (lo + hi) >> 1;
            int sgv = seg[m];
            int key = (sgv % NLAT) * KS + (sgv / NLAT);
            if (key < j) lo = m + 1; else hi = m;
        }
        sb[k] = lo;
    }

    const int wlim = (t + 1) * WSLOT;
    int wabs = 0, rbase = 0;
    int entc = 0, runsc = 0;

    for (int pass = 0; pass < 2; pass++) {
        int ent = 0, runs = 0;
        for (int la = lane; la < NLAT; la += 32) {
            int bks[3], eks[3];
            #pragma unroll
            for (int k = 0; k < 3; k++) {
                int lo = sb[k], hi = sb[k + 1];
                while (lo < hi) { int m = (lo + hi) >> 1; if (lat[m] < la) lo = m + 1; else hi = m; }
                bks[k] = lo;
                hi = sb[k + 1];
                while (lo < hi) { int m = (lo + hi) >> 1; if (lat[m] < la + 1) lo = m + 1; else hi = m; }
                eks[k] = lo;
            }
            int p0 = bks[0], p1 = bks[1], p2 = bks[2];
            const float q = qw[la];
            int prev = -2, rstart = ent, rcnt = 0, rlo0 = 0;
            while (p0 < eks[0] || p1 < eks[1] || p2 < eks[2]) {
                int l0 = (p0 < eks[0]) ? lon[p0] : 0x7fffffff;
                int l1 = (p1 < eks[1]) ? lon[p1] : 0x7fffffff;
                int l2 = (p2 < eks[2]) ? lon[p2] : 0x7fffffff;
                int lm = min(l0, min(l1, l2));
                float w0 = 0.f, w1 = 0.f, w2 = 0.f;
                if (l0 == lm) { w0 = vals[p0] * q; p0++; }
                if (l1 == lm) { w1 = vals[p1] * q; p1++; }
                if (l2 == lm) { w2 = vals[p2] * q; p2++; }
                if (w0 == 0.f && w1 == 0.f && w2 == 0.f) continue;
                if (rcnt > 0 && lm != prev + 1) {
                    int pad = (4 - (rcnt & 3)) & 3;
                    if (pass == 1) {
                        for (int z = 0; z < pad; z++) {
                            int ai = wabs + rstart + rcnt + z;
                            if (ai < wlim) g_rw[ai] = make_float4(0.f, 0.f, 0.f, 0.f);
                        }
                        int ri = rbase + runs;
                        if (ri < RSLOT)
                            g_runs[t * RSLOT + ri] =
                                make_int4(la, rlo0, rcnt + pad, wabs + rstart);
                    }
                    runs++;
                    ent = rstart + rcnt + pad;
                    rstart = ent; rcnt = 0;
                }
                if (rcnt == 0) rlo0 = lm;
                if (pass == 1) {
                    int ai = wabs + rstart + rcnt;
                    if (ai < wlim) g_rw[ai] = make_float4(w0, w1, w2, 0.f);
                }
                rcnt++;
                ent = rstart + rcnt;
                prev = lm;
            }
            if (rcnt > 0) {
                int pad = (4 - (rcnt & 3)) & 3;
                if (pass == 1) {
                    for (int z = 0; z < pad; z++) {
                        int ai = wabs + rstart + rcnt + z;
                        if (ai < wlim) g_rw[ai] = make_float4(0.f, 0.f, 0.f, 0.f);
                    }
                    int ri = rbase + runs;
                    if (ri < RSLOT)
                        g_runs[t * RSLOT + ri] =
                            make_int4(la, rlo0, rcnt + pad, wabs + rstart);
                }
                runs++;
                ent = rstart + rcnt + pad;
            }
        }
        if (pass == 0) {
            entc = ent; runsc = runs;
            int ei = entc, ri = runsc;
            #pragma unroll
            for (int d = 1; d < 32; d <<= 1) {
                int v = __shfl_up_sync(0xffffffffu, ei, d);
                int u = __shfl_up_sync(0xffffffffu, ri, d);
                if (lane >= d) { ei += v; ri += u; }
            }
            wabs  = t * WSLOT + (ei - entc);
            rbase = ri - runsc;
            if (lane == 31) g_rcnt[t] = min(ri, RSLOT);
        }
    }
}

// ---------------------------------------------------------------------------
// Stage 1: gather with rolling column window. Writes z M-major g_z[m][ck],
// tf32-RN-rounded for the mma stage.
// ---------------------------------------------------------------------------
__global__ void __launch_bounds__(256, 2)
gather_kernel() {
    const int tid  = threadIdx.x;
    const int warp = tid >> 5;
    const int lane = tid & 31;

    const int yb = blockIdx.y;
    const int t  = (yb & 1) ? (NLAT - 1 - (yb >> 1)) : (yb >> 1);   // pole-first
    const int b  = blockIdx.z;
    const int p0 = blockIdx.x * PT;
    const int pbase = p0 + warp * 4;

    const int nruns = g_rcnt[t];
    const int4* runs = g_runs + (size_t)t * RSLOT;
    const float4* xb = (const float4*)(g_xt + (size_t)b * CHW * CIN);

    unsigned long long a2[3][4][2];
    #pragma unroll
    for (int k = 0; k < 3; k++)
        #pragma unroll
        for (int q = 0; q < 4; q++) { a2[k][q][0] = 0ull; a2[k][q][1] = 0ull; }

    for (int r = 0; r < nruns; r++) {
        const int4 rn = __ldg(&runs[r]);
        const int la   = rn.x;
        const int cnt  = rn.z;
        const float4* wp = g_rw + rn.w;
        const int rowb = la * NLON;

        int col = rn.y + pbase;
        if (col >= NLON) col -= NLON;
        if (col >= NLON) col -= NLON;
        int c1 = col + 1; if (c1 >= NLON) c1 -= NLON;
        int c2 = c1 + 1;  if (c2 >= NLON) c2 -= NLON;

        F4U w0v, w1v, w2v;
        w0v.f = xb[(size_t)(rowb + col) * 32 + lane];
        w1v.f = xb[(size_t)(rowb + c1)  * 32 + lane];
        w2v.f = xb[(size_t)(rowb + c2)  * 32 + lane];
        int colx = c2;

        for (int j4 = 0; j4 < cnt; j4 += 4) {
            int n0 = colx + 1; if (n0 >= NLON) n0 -= NLON;
            int n1 = colx + 2; if (n1 >= NLON) n1 -= NLON;
            int n2 = colx + 3; if (n2 >= NLON) n2 -= NLON;
            int n3 = colx + 4; if (n3 >= NLON) n3 -= NLON;
            colx = n3;
            F4U nw0, nw1, nw2, nw3;
            nw0.f = xb[(size_t)(rowb + n0) * 32 + lane];
            nw1.f = xb[(size_t)(rowb + n1) * 32 + lane];
            nw2.f = xb[(size_t)(rowb + n2) * 32 + lane];
            nw3.f = xb[(size_t)(rowb + n3) * 32 + lane];

            float4 wa = __ldg(&wp[j4 + 0]);
            float4 wb = __ldg(&wp[j4 + 1]);
            float4 wc = __ldg(&wp[j4 + 2]);
            float4 wd = __ldg(&wp[j4 + 3]);

            #define DO_ENTRY(W, V0, V1, V2, V3)                                   \
            {                                                                     \
                unsigned long long k0 = pack2(W.x, W.x);                          \
                unsigned long long k1 = pack2(W.y, W.y);                          \
                unsigned long long k2 = pack2(W.z, W.z);                          \
                fma2(a2[0][0][0], k0, V0.u[0]); fma2(a2[0][0][1], k0, V0.u[1]);   \
                fma2(a2[1][0][0], k1, V0.u[0]); fma2(a2[1][0][1], k1, V0.u[1]);   \
                fma2(a2[2][0][0], k2, V0.u[0]); fma2(a2[2][0][1], k2, V0.u[1]);   \
                fma2(a2[0][1][0], k0, V1.u[0]); fma2(a2[0][1][1], k0, V1.u[1]);   \
                fma2(a2[1][1][0], k1, V1.u[0]); fma2(a2[1][1][1], k1, V1.u[1]);   \
                fma2(a2[2][1][0], k2, V1.u[0]); fma2(a2[2][1][1], k2, V1.u[1]);   \
                fma2(a2[0][2][0], k0, V2.u[0]); fma2(a2[0][2][1], k0, V2.u[1]);   \
                fma2(a2[1][2][0], k1, V2.u[0]); fma2(a2[1][2][1], k1, V2.u[1]);   \
                fma2(a2[2][2][0], k2, V2.u[0]); fma2(a2[2][2][1], k2, V2.u[1]);   \
                fma2(a2[0][3][0], k0, V3.u[0]); fma2(a2[0][3][1], k0, V3.u[1]);   \
                fma2(a2[1][3][0], k1, V3.u[0]); fma2(a2[1][3][1], k1, V3.u[1]);   \
                fma2(a2[2][3][0], k2, V3.u[0]); fma2(a2[2][3][1], k2, V3.u[1]);   \
            }
            DO_ENTRY(wa, w0v, w1v, w2v, nw0)
            DO_ENTRY(wb, w1v, w2v, nw0, nw1)
            DO_ENTRY(wc, w2v, nw0, nw1, nw2)
            DO_ENTRY(wd, nw0, nw1, nw2, nw3)
            #undef DO_ENTRY
            w0v = nw1; w1v = nw2; w2v = nw3;
        }
    }

    // store z[m][ck] (tf32-rounded): ck = (lane*4 + c)*3 + k
    if (pbase < NLON) {
        const size_t mb = (size_t)(b * NLAT + t) * NLON + pbase;
        #pragma unroll
        for (int q = 0; q < 4; q++) {
            float* zp = g_z + (mb + q) * (size_t)CK + lane * 12;
            U2F x00, x10, x20, x01, x11, x21;
            x00.u = a2[0][q][0]; x10.u = a2[1][q][0]; x20.u = a2[2][q][0];
            x01.u = a2[0][q][1]; x11.u = a2[1][q][1]; x21.u = a2[2][q][1];
            *(float4*)(zp + 0) = make_float4(tf32r(x00.f.x), tf32r(x10.f.x),
                                             tf32r(x20.f.x), tf32r(x00.f.y));
            *(float4*)(zp + 4) = make_float4(tf32r(x10.f.y), tf32r(x20.f.y),
                                             tf32r(x01.f.x), tf32r(x11.f.x));
            *(float4*)(zp + 8) = make_float4(tf32r(x21.f.x), tf32r(x01.f.y),
                                             tf32r(x11.f.y), tf32r(x21.f.y));
        }
    }
}

// ---------------------------------------------------------------------------
// Stage 2: mma.sync tf32 GEMM with ldmatrix fragment loads.
// Per CTA: D[128m x 128f] = z[128m x 384] @ W^T, cp.async double-buffered.
// Per k-step per warp: 2 A-ldmatrix.x4 + 4 B-ldmatrix.x4 + 16 mma.
// ---------------------------------------------------------------------------
__global__ void __launch_bounds__(256, 2)
gemm_mma_kernel(const float* __restrict__ bias, float* __restrict__ out) {
    extern __shared__ float smem[];     // [2][ (A:128*36) + (B:128*36) ]
    __shared__ float s_bias[COUT];

    const int tid  = threadIdx.x;
    const int warp = tid >> 5;
    const int lane = tid & 31;
    const int g    = lane >> 2;
    const int tg   = lane & 3;
    const int wm   = warp & 3;          // m-warp (4 x 32 rows)
    const int wn   = warp >> 2;         // f-warp (2 x 64 cols)
    const int m0   = blockIdx.x * MTILE;

    const uint32_t sbase = smem_u32(smem);
    const int lr = tid >> 3;            // load row group 0..31
    const int lc = tid & 7;             // float4 col 0..7

    if (tid < COUT) s_bias[tid] = __ldg(bias + tid);

    // ldmatrix per-lane base addresses (bytes), before buffer/k offsets.
    // addr word = (row0 + (lane&15))*SROW + (lane>>4)*4
    const uint32_t lrow = (uint32_t)(lane & 15);
    const uint32_t lcg  = (uint32_t)(lane >> 4) * 4;
    uint32_t a_adr[2], b_adr[4];
    #pragma unroll
    for (int mt = 0; mt < 2; mt++)
        a_adr[mt] = sbase + ((wm * 32 + mt * 16 + lrow) * SROW + lcg) * 4;
    #pragma unroll
    for (int pr = 0; pr < 4; pr++)
        b_adr[pr] = sbase + ((128 + wn * 64 + pr * 16 + lrow) * SROW + lcg) * 4;

    float acc[2][8][4];
    #pragma unroll
    for (int mt = 0; mt < 2; mt++)
        #pragma unroll
        for (int nt = 0; nt < 8; nt++)
            #pragma unroll
            for (int i = 0; i < 4; i++) acc[mt][nt][i] = 0.f;

    #define LOAD_CHUNK(CH, BUFI)                                                   \
    {                                                                              \
        const uint32_t sa = sbase + (uint32_t)(BUFI) * (2 * 128 * SROW * 4);       \
        const uint32_t sb = sa + 128 * SROW * 4;                                   \
        _Pragma("unroll")                                                          \
        for (int i = 0; i < 4; i++) {                                              \
            const int row = lr + i * 32;                                           \
            const uint32_t so = (uint32_t)(row * SROW + lc * 4) * 4;               \
            cpasync16(sa + so, &g_z[(size_t)(m0 + row) * CK + (CH) * KCH + lc * 4]); \
            cpasync16(sb + so, &g_wtf[row * CK + (CH) * KCH + lc * 4]);            \
        }                                                                          \
        cp_commit();                                                               \
    }

    LOAD_CHUNK(0, 0)

    for (int ch = 0; ch < NCH; ch++) {
        if (ch + 1 < NCH) { LOAD_CHUNK(ch + 1, (ch + 1) & 1) }
        if (ch + 1 < NCH) cp_wait<1>(); else cp_wait<0>();
        __syncthreads();

        const uint32_t bufo = (uint32_t)(ch & 1) * (2 * 128 * SROW * 4);

        #pragma unroll
        for (int ks = 0; ks < 4; ks++) {
            const uint32_t ko = bufo + ks * 32;   // k0 = ks*8 words = 32 bytes
            uint32_t afr[2][4];
            #pragma unroll
            for (int mt = 0; mt < 2; mt++)
                ldsm_x4(afr[mt][0], afr[mt][1], afr[mt][2], afr[mt][3],
                        a_adr[mt] + ko);
            #pragma unroll
            for (int pr = 0; pr < 4; pr++) {
                uint32_t b00, b01, b10, b11;   // {b0 nt even, b0 nt odd, b1 even, b1 odd}
                ldsm_x4(b00, b01, b10, b11, b_adr[pr] + ko);
                uint32_t bf0[2] = { b00, b10 };
                uint32_t bf1[2] = { b01, b11 };
                mma_tf32(acc[0][2 * pr],     afr[0], bf0[0], bf0[1]);
                mma_tf32(acc[1][2 * pr],     afr[1], bf0[0], bf0[1]);
                mma_tf32(acc[0][2 * pr + 1], afr[0], bf1[0], bf1[1]);
                mma_tf32(acc[1][2 * pr + 1], afr[1], bf1[0], bf1[1]);
            }
        }
        __syncthreads();
    }

    // Epilogue: D[m][f] -> out[b][f][t][p] with bias.
    #pragma unroll
    for (int mt = 0; mt < 2; mt++) {
        const int mlo = m0 + wm * 32 + mt * 16 + g;
        const int mhi = mlo + 8;
        const bool vlo = (mlo < MTOT), vhi = (mhi < MTOT);
        float* plo = nullptr;
        float* phi = nullptr;
        if (vlo) { int bb = mlo / CHW; plo = out + (size_t)bb * COUT * CHW + (mlo - bb * CHW); }
        if (vhi) { int bb = mhi / CHW; phi = out + (size_t)bb * COUT * CHW + (mhi - bb * CHW); }
        #pragma unroll
        for (int nt = 0; nt < 8; nt++) {
            const int f0 = wn * 64 + nt * 8 + tg * 2;
            const float b0 = s_bias[f0], b1 = s_bias[f0 + 1];
            if (vlo) {
                plo[(size_t)f0 * CHW]       = acc[mt][nt][0] + b0;
                plo[(size_t)(f0 + 1) * CHW] = acc[mt][nt][1] + b1;
            }
            if (vhi) {
                phi[(size_t)f0 * CHW]       = acc[mt][nt][2] + b0;
                phi[(size_t)(f0 + 1) * CHW] = acc[mt][nt][3] + b1;
            }
        }
    }
    #undef LOAD_CHUNK
}

// ---------------------------------------------------------------------------
// Launch.
// ---------------------------------------------------------------------------
extern "C" void kernel_launch(void* const* d_in, const int* in_sizes, int n_in,
                              void* d_out, int out_size) {
    const float* x      = (const float*)d_in[0];
    const float* qw     = (const float*)d_in[1];
    const float* vals   = (const float*)d_in[2];
    const float* weight = (const float*)d_in[3];
    const float* bias   = (const float*)d_in[4];
    const int*   seg    = (const int*)d_in[5];
    const int*   lat    = (const int*)d_in[6];
    const int*   lon    = (const int*)d_in[7];
    const int    nnz    = in_sizes[2];

    dim3 tgrid((CHW + 31) / 32, CIN / 32, BSZ);
    transpose_kernel<<<tgrid, dim3(32, 8)>>>(x);
    wconv_kernel<<<(COUT * CK + 255) / 256, 256>>>(weight);
    merge_kernel<<<(NLAT * 32 + 127) / 128, 128>>>(seg, lat, lon, vals, qw, nnz);

    dim3 ggrid(NPT, NLAT, BSZ);
    gather_kernel<<<ggrid, 256>>>();

    const int dyn_bytes = 2 * 2 * 128 * SROW * sizeof(float);   // 73728
    cudaFuncSetAttribute(gemm_mma_kernel,
                         cudaFuncAttributeMaxDynamicSharedMemorySize, dyn_bytes);
    gemm_mma_kernel<<<MBLK, 256, dyn_bytes>>>(bias, (float*)d_out);
}

// round 9
// speedup vs baseline: 1.0117x; 1.0117x over previous
#include <cuda_runtime.h>
#include <cstdint>

// Problem constants
#define NLAT 181
#define NLON 360
#define CIN  128
#define COUT 128
#define KS   3
#define BSZ  2
#define CHW  (NLAT * NLON)     // 65160
#define CK   (CIN * KS)        // 384
#define PT   32                // gather p-tile
#define NPT  12
#define MTOT  (BSZ * CHW)      // 130320
#define MTILE 128
#define MBLK  ((MTOT + MTILE - 1) / MTILE)   // 1019
#define MPADL (MBLK * MTILE)                 // 130432
#define WSLOT 4096
#define RSLOT 512
#define KCH   32               // GEMM K-chunk
#define NCH   (CK / KCH)       // 12
#define SROW  36               // padded smem row (words), conflict-free ldmatrix
#define BUFW  (2 * 128 * SROW) // words per stage buffer (A+B)
#define NSTG  3                // cp.async stages

// Scratch (device globals — allocation-free; zero-init so padded z rows are 0)
__device__ float  g_xt[(size_t)BSZ * CHW * CIN];   // x transposed: [b][h*w][c]
__device__ float4 g_rw[NLAT * WSLOT];              // run weights {w0,w1,w2,0}
__device__ int4   g_runs[NLAT * RSLOT];            // {la, lo0, cnt_padded, wabs}
__device__ int    g_rcnt[NLAT];
__device__ float  g_z[(size_t)MPADL * CK];         // z M-major [m][ck], tf32-rounded
__device__ float  g_wtf[COUT * CK];                // W [f][ck], tf32-rounded

// ---------------- helpers ----------------
__device__ __forceinline__ void fma2(unsigned long long& d,
                                     unsigned long long a,
                                     unsigned long long b) {
    asm("fma.rn.f32x2 %0, %1, %2, %0;" : "+l"(d) : "l"(a), "l"(b));
}
__device__ __forceinline__ unsigned long long pack2(float x, float y) {
    unsigned long long r;
    asm("mov.b64 %0, {%1, %2};" : "=l"(r) : "f"(x), "f"(y));
    return r;
}
union F4U { float4 f; unsigned long long u[2]; };
union U2F { unsigned long long u; float2 f; };

__device__ __forceinline__ float tf32r(float x) {
    uint32_t r;
    asm("cvt.rn.tf32.f32 %0, %1;" : "=r"(r) : "f"(x));
    return __uint_as_float(r);
}
__device__ __forceinline__ uint32_t smem_u32(const void* p) {
    uint32_t a;
    asm("{ .reg .u64 t; cvta.to.shared.u64 t, %1; cvt.u32.u64 %0, t; }"
        : "=r"(a) : "l"(p));
    return a;
}
__device__ __forceinline__ void cpasync16(uint32_t s, const void* g) {
    asm volatile("cp.async.cg.shared.global [%0], [%1], 16;" :: "r"(s), "l"(g));
}
__device__ __forceinline__ void cp_commit() {
    asm volatile("cp.async.commit_group;" ::: "memory");
}
template <int N>
__device__ __forceinline__ void cp_wait() {
    asm volatile("cp.async.wait_group %0;" :: "n"(N) : "memory");
}
__device__ __forceinline__ void mma_tf32(float* d, const uint32_t* a,
                                         uint32_t b0, uint32_t b1) {
    asm volatile(
        "mma.sync.aligned.m16n8k8.row.col.f32.tf32.tf32.f32 "
        "{%0,%1,%2,%3}, {%4,%5,%6,%7}, {%8,%9}, {%0,%1,%2,%3};"
        : "+f"(d[0]), "+f"(d[1]), "+f"(d[2]), "+f"(d[3])
        : "r"(a[0]), "r"(a[1]), "r"(a[2]), "r"(a[3]), "r"(b0), "r"(b1));
}
__device__ __forceinline__ void ldsm_x4(uint32_t& r0, uint32_t& r1,
                                        uint32_t& r2, uint32_t& r3, uint32_t addr) {
    asm volatile("ldmatrix.sync.aligned.m8n8.x4.shared.b16 {%0,%1,%2,%3}, [%4];"
                 : "=r"(r0), "=r"(r1), "=r"(r2), "=r"(r3) : "r"(addr));
}

// ---------------------------------------------------------------------------
// Transpose x[b][c][hw] -> g_xt[b][hw][c]
// ---------------------------------------------------------------------------
__global__ void transpose_kernel(const float* __restrict__ x) {
    __shared__ float tile[32][33];
    const int hw0 = blockIdx.x * 32;
    const int c0  = blockIdx.y * 32;
    const int b   = blockIdx.z;
    const int tx = threadIdx.x, ty = threadIdx.y;
    #pragma unroll
    for (int i = 0; i < 4; i++) {
        int c  = c0 + ty + i * 8;
        int hw = hw0 + tx;
        if (hw < CHW)
            tile[ty + i * 8][tx] = x[((size_t)b * CIN + c) * CHW + hw];
    }
    __syncthreads();
    #pragma unroll
    for (int i = 0; i < 4; i++) {
        int hw = hw0 + ty + i * 8;
        int c  = c0 + tx;
        if (hw < CHW)
            g_xt[((size_t)b * CHW + hw) * CIN + c] = tile[tx][ty + i * 8];
    }
}

// W[f][ck] -> tf32-rounded copy
__global__ void wconv_kernel(const float* __restrict__ w) {
    int i = blockIdx.x * 256 + threadIdx.x;
    if (i < COUT * CK) g_wtf[i] = tf32r(w[i]);
}

// ---------------------------------------------------------------------------
// Merge: warp per t. Emits per-(t,la) runs of consecutive lons with
// branch-free weight triples, zero-padded to multiples of 4 entries.
// ---------------------------------------------------------------------------
__global__ void merge_kernel(const int* __restrict__ seg,
                             const int* __restrict__ lat,
                             const int* __restrict__ lon,
                             const float* __restrict__ vals,
                             const float* __restrict__ qw,
                             int nnz) {
    const int t    = (blockIdx.x * blockDim.x + threadIdx.x) >> 5;
    const int lane = threadIdx.x & 31;
    if (t >= NLAT) return;

    int sb[4];
    #pragma unroll
    for (int k = 0; k < 4; k++) {
        const int j = t * KS + k;
        int lo = 0, hi = nnz;
        while (lo < hi) {
            int m = (lo + hi) >> 1;
            int sgv = seg[m];
            int key = (sgv % NLAT) * KS + (sgv / NLAT);
            if (key < j) lo = m + 1; else hi = m;
        }
        sb[k] = lo;
    }

    const int wlim = (t + 1) * WSLOT;
    int wabs = 0, rbase = 0;
    int entc = 0, runsc = 0;

    for (int pass = 0; pass < 2; pass++) {
        int ent = 0, runs = 0;
        for (int la = lane; la < NLAT; la += 32) {
            int bks[3], eks[3];
            #pragma unroll
            for (int k = 0; k < 3; k++) {
                int lo = sb[k], hi = sb[k + 1];
                while (lo < hi) { int m = (lo + hi) >> 1; if (lat[m] < la) lo = m + 1; else hi = m; }
                bks[k] = lo;
                hi = sb[k + 1];
                while (lo < hi) { int m = (lo + hi) >> 1; if (lat[m] < la + 1) lo = m + 1; else hi = m; }
                eks[k] = lo;
            }
            int p0 = bks[0], p1 = bks[1], p2 = bks[2];
            const float q = qw[la];
            int prev = -2, rstart = ent, rcnt = 0, rlo0 = 0;
            while (p0 < eks[0] || p1 < eks[1] || p2 < eks[2]) {
                int l0 = (p0 < eks[0]) ? lon[p0] : 0x7fffffff;
                int l1 = (p1 < eks[1]) ? lon[p1] : 0x7fffffff;
                int l2 = (p2 < eks[2]) ? lon[p2] : 0x7fffffff;
                int lm = min(l0, min(l1, l2));
                float w0 = 0.f, w1 = 0.f, w2 = 0.f;
                if (l0 == lm) { w0 = vals[p0] * q; p0++; }
                if (l1 == lm) { w1 = vals[p1] * q; p1++; }
                if (l2 == lm) { w2 = vals[p2] * q; p2++; }
                if (w0 == 0.f && w1 == 0.f && w2 == 0.f) continue;
                if (rcnt > 0 && lm != prev + 1) {
                    int pad = (4 - (rcnt & 3)) & 3;
                    if (pass == 1) {
                        for (int z = 0; z < pad; z++) {
                            int ai = wabs + rstart + rcnt + z;
                            if (ai < wlim) g_rw[ai] = make_float4(0.f, 0.f, 0.f, 0.f);
                        }
                        int ri = rbase + runs;
                        if (ri < RSLOT)
                            g_runs[t * RSLOT + ri] =
                                make_int4(la, rlo0, rcnt + pad, wabs + rstart);
                    }
                    runs++;
                    ent = rstart + rcnt + pad;
                    rstart = ent; rcnt = 0;
                }
                if (rcnt == 0) rlo0 = lm;
                if (pass == 1) {
                    int ai = wabs + rstart + rcnt;
                    if (ai < wlim) g_rw[ai] = make_float4(w0, w1, w2, 0.f);
                }
                rcnt++;
                ent = rstart + rcnt;
                prev = lm;
            }
            if (rcnt > 0) {
                int pad = (4 - (rcnt & 3)) & 3;
                if (pass == 1) {
                    for (int z = 0; z < pad; z++) {
                        int ai = wabs + rstart + rcnt + z;
                        if (ai < wlim) g_rw[ai] = make_float4(0.f, 0.f, 0.f, 0.f);
                    }
                    int ri = rbase + runs;
                    if (ri < RSLOT)
                        g_runs[t * RSLOT + ri] =
                            make_int4(la, rlo0, rcnt + pad, wabs + rstart);
                }
                runs++;
                ent = rstart + rcnt + pad;
            }
        }
        if (pass == 0) {
            entc = ent; runsc = runs;
            int ei = entc, ri = runsc;
            #pragma unroll
            for (int d = 1; d < 32; d <<= 1) {
                int v = __shfl_up_sync(0xffffffffu, ei, d);
                int u = __shfl_up_sync(0xffffffffu, ri, d);
                if (lane >= d) { ei += v; ri += u; }
            }
            wabs  = t * WSLOT + (ei - entc);
            rbase = ri - runsc;
            if (lane == 31) g_rcnt[t] = min(ri, RSLOT);
        }
    }
}

// ---------------------------------------------------------------------------
// Stage 1: gather with rolling column window. Writes z M-major g_z[m][ck],
// tf32-RN-rounded for the mma stage.
// ---------------------------------------------------------------------------
__global__ void __launch_bounds__(256, 2)
gather_kernel() {
    const int tid  = threadIdx.x;
    const int warp = tid >> 5;
    const int lane = tid & 31;

    const int yb = blockIdx.y;
    const int t  = (yb & 1) ? (NLAT - 1 - (yb >> 1)) : (yb >> 1);   // pole-first
    const int b  = blockIdx.z;
    const int p0 = blockIdx.x * PT;
    const int pbase = p0 + warp * 4;

    const int nruns = g_rcnt[t];
    const int4* runs = g_runs + (size_t)t * RSLOT;
    const float4* xb = (const float4*)(g_xt + (size_t)b * CHW * CIN);

    unsigned long long a2[3][4][2];
    #pragma unroll
    for (int k = 0; k < 3; k++)
        #pragma unroll
        for (int q = 0; q < 4; q++) { a2[k][q][0] = 0ull; a2[k][q][1] = 0ull; }

    for (int r = 0; r < nruns; r++) {
        const int4 rn = __ldg(&runs[r]);
        const int la   = rn.x;
        const int cnt  = rn.z;
        const float4* wp = g_rw + rn.w;
        const int rowb = la * NLON;

        int col = rn.y + pbase;
        if (col >= NLON) col -= NLON;
        if (col >= NLON) col -= NLON;
        int c1 = col + 1; if (c1 >= NLON) c1 -= NLON;
        int c2 = c1 + 1;  if (c2 >= NLON) c2 -= NLON;

        F4U w0v, w1v, w2v;
        w0v.f = xb[(size_t)(rowb + col) * 32 + lane];
        w1v.f = xb[(size_t)(rowb + c1)  * 32 + lane];
        w2v.f = xb[(size_t)(rowb + c2)  * 32 + lane];
        int colx = c2;

        for (int j4 = 0; j4 < cnt; j4 += 4) {
            int n0 = colx + 1; if (n0 >= NLON) n0 -= NLON;
            int n1 = colx + 2; if (n1 >= NLON) n1 -= NLON;
            int n2 = colx + 3; if (n2 >= NLON) n2 -= NLON;
            int n3 = colx + 4; if (n3 >= NLON) n3 -= NLON;
            colx = n3;
            F4U nw0, nw1, nw2, nw3;
            nw0.f = xb[(size_t)(rowb + n0) * 32 + lane];
            nw1.f = xb[(size_t)(rowb + n1) * 32 + lane];
            nw2.f = xb[(size_t)(rowb + n2) * 32 + lane];
            nw3.f = xb[(size_t)(rowb + n3) * 32 + lane];

            float4 wa = __ldg(&wp[j4 + 0]);
            float4 wb = __ldg(&wp[j4 + 1]);
            float4 wc = __ldg(&wp[j4 + 2]);
            float4 wd = __ldg(&wp[j4 + 3]);

            #define DO_ENTRY(W, V0, V1, V2, V3)                                   \
            {                                                                     \
                unsigned long long k0 = pack2(W.x, W.x);                          \
                unsigned long long k1 = pack2(W.y, W.y);                          \
                unsigned long long k2 = pack2(W.z, W.z);                          \
                fma2(a2[0][0][0], k0, V0.u[0]); fma2(a2[0][0][1], k0, V0.u[1]);   \
                fma2(a2[1][0][0], k1, V0.u[0]); fma2(a2[1][0][1], k1, V0.u[1]);   \
                fma2(a2[2][0][0], k2, V0.u[0]); fma2(a2[2][0][1], k2, V0.u[1]);   \
                fma2(a2[0][1][0], k0, V1.u[0]); fma2(a2[0][1][1], k0, V1.u[1]);   \
                fma2(a2[1][1][0], k1, V1.u[0]); fma2(a2[1][1][1], k1, V1.u[1]);   \
                fma2(a2[2][1][0], k2, V1.u[0]); fma2(a2[2][1][1], k2, V1.u[1]);   \
                fma2(a2[0][2][0], k0, V2.u[0]); fma2(a2[0][2][1], k0, V2.u[1]);   \
                fma2(a2[1][2][0], k1, V2.u[0]); fma2(a2[1][2][1], k1, V2.u[1]);   \
                fma2(a2[2][2][0], k2, V2.u[0]); fma2(a2[2][2][1], k2, V2.u[1]);   \
                fma2(a2[0][3][0], k0, V3.u[0]); fma2(a2[0][3][1], k0, V3.u[1]);   \
                fma2(a2[1][3][0], k1, V3.u[0]); fma2(a2[1][3][1], k1, V3.u[1]);   \
                fma2(a2[2][3][0], k2, V3.u[0]); fma2(a2[2][3][1], k2, V3.u[1]);   \
            }
            DO_ENTRY(wa, w0v, w1v, w2v, nw0)
            DO_ENTRY(wb, w1v, w2v, nw0, nw1)
            DO_ENTRY(wc, w2v, nw0, nw1, nw2)
            DO_ENTRY(wd, nw0, nw1, nw2, nw3)
            #undef DO_ENTRY
            w0v = nw1; w1v = nw2; w2v = nw3;
        }
    }

    // store z[m][ck] (tf32-rounded): ck = (lane*4 + c)*3 + k
    if (pbase < NLON) {
        const size_t mb = (size_t)(b * NLAT + t) * NLON + pbase;
        #pragma unroll
        for (int q = 0; q < 4; q++) {
            float* zp = g_z + (mb + q) * (size_t)CK + lane * 12;
            U2F x00, x10, x20, x01, x11, x21;
            x00.u = a2[0][q][0]; x10.u = a2[1][q][0]; x20.u = a2[2][q][0];
            x01.u = a2[0][q][1]; x11.u = a2[1][q][1]; x21.u = a2[2][q][1];
            *(float4*)(zp + 0) = make_float4(tf32r(x00.f.x), tf32r(x10.f.x),
                                             tf32r(x20.f.x), tf32r(x00.f.y));
            *(float4*)(zp + 4) = make_float4(tf32r(x10.f.y), tf32r(x20.f.y),
                                             tf32r(x01.f.x), tf32r(x11.f.x));
            *(float4*)(zp + 8) = make_float4(tf32r(x21.f.x), tf32r(x01.f.y),
                                             tf32r(x11.f.y), tf32r(x21.f.y));
        }
    }
}

// ---------------------------------------------------------------------------
// Stage 2: mma.sync tf32 GEMM, 3-stage cp.async pipeline, ONE sync per chunk.
// Per iter: wait(chunk ch) -> sync -> issue load(ch+2) -> compute(ch).
// Buffer (ch+2)%3 is disjoint from the compute buffer ch%3 and the in-flight
// (ch+1)%3; WAR against compute(ch-1) is ordered by this iteration's sync.
// ---------------------------------------------------------------------------
__global__ void __launch_bounds__(256, 2)
gemm_mma_kernel(const float* __restrict__ bias, float* __restrict__ out) {
    extern __shared__ float smem[];     // [NSTG][BUFW]
    __shared__ float s_bias[COUT];

    const int tid  = threadIdx.x;
    const int warp = tid >> 5;
    const int lane = tid & 31;
    const int g    = lane >> 2;
    const int tg   = lane & 3;
    const int wm   = warp & 3;          // m-warp (4 x 32 rows)
    const int wn   = warp >> 2;         // f-warp (2 x 64 cols)
    const int m0   = blockIdx.x * MTILE;

    const uint32_t sbase = smem_u32(smem);
    const int lr = tid >> 3;            // load row group 0..31
    const int lc = tid & 7;             // float4 col 0..7

    if (tid < COUT) s_bias[tid] = __ldg(bias + tid);

    // ldmatrix per-lane base addresses (bytes), before buffer/k offsets.
    const uint32_t lrow = (uint32_t)(lane & 15);
    const uint32_t lcg  = (uint32_t)(lane >> 4) * 4;
    uint32_t a_adr[2], b_adr[4];
    #pragma unroll
    for (int mt = 0; mt < 2; mt++)
        a_adr[mt] = sbase + ((wm * 32 + mt * 16 + lrow) * SROW + lcg) * 4;
    #pragma unroll
    for (int pr = 0; pr < 4; pr++)
        b_adr[pr] = sbase + ((128 + wn * 64 + pr * 16 + lrow) * SROW + lcg) * 4;

    float acc[2][8][4];
    #pragma unroll
    for (int mt = 0; mt < 2; mt++)
        #pragma unroll
        for (int nt = 0; nt < 8; nt++)
            #pragma unroll
            for (int i = 0; i < 4; i++) acc[mt][nt][i] = 0.f;

    #define LOAD_CHUNK(CH, BUFI)                                                   \
    {                                                                              \
        const uint32_t sa = sbase + (uint32_t)(BUFI) * (BUFW * 4);                 \
        const uint32_t sb = sa + 128 * SROW * 4;                                   \
        _Pragma("unroll")                                                          \
        for (int i = 0; i < 4; i++) {                                              \
            const int row = lr + i * 32;                                           \
            const uint32_t so = (uint32_t)(row * SROW + lc * 4) * 4;               \
            cpasync16(sa + so, &g_z[(size_t)(m0 + row) * CK + (CH) * KCH + lc * 4]); \
            cpasync16(sb + so, &g_wtf[row * CK + (CH) * KCH + lc * 4]);            \
        }                                                                          \
        cp_commit();                                                               \
    }

    LOAD_CHUNK(0, 0)
    LOAD_CHUNK(1, 1)

    for (int ch = 0; ch < NCH; ch++) {
        if (ch + 1 < NCH) cp_wait<1>(); else cp_wait<0>();
        __syncthreads();
        if (ch + 2 < NCH) { LOAD_CHUNK(ch + 2, (ch + 2) % NSTG) }

        const uint32_t bufo = (uint32_t)(ch % NSTG) * (BUFW * 4);
        #pragma unroll
        for (int ks = 0; ks < 4; ks++) {
            const uint32_t ko = bufo + ks * 32;   // k0 = ks*8 words = 32 bytes
            uint32_t afr[2][4];
            #pragma unroll
            for (int mt = 0; mt < 2; mt++)
                ldsm_x4(afr[mt][0], afr[mt][1], afr[mt][2], afr[mt][3],
                        a_adr[mt] + ko);
            #pragma unroll
            for (int pr = 0; pr < 4; pr++) {
                uint32_t b00, b01, b10, b11;
                ldsm_x4(b00, b01, b10, b11, b_adr[pr] + ko);
                mma_tf32(acc[0][2 * pr],     afr[0], b00, b10);
                mma_tf32(acc[1][2 * pr],     afr[1], b00, b10);
                mma_tf32(acc[0][2 * pr + 1], afr[0], b01, b11);
                mma_tf32(acc[1][2 * pr + 1], afr[1], b01, b11);
            }
        }
    }

    // Epilogue: D[m][f] -> out[b][f][t][p] with bias.
    #pragma unroll
    for (int mt = 0; mt < 2; mt++) {
        const int mlo = m0 + wm * 32 + mt * 16 + g;
        const int mhi = mlo + 8;
        const bool vlo = (mlo < MTOT), vhi = (mhi < MTOT);
        float* plo = nullptr;
        float* phi = nullptr;
        if (vlo) { int bb = mlo / CHW; plo = out + (size_t)bb * COUT * CHW + (mlo - bb * CHW); }
        if (vhi) { int bb = mhi / CHW; phi = out + (size_t)bb * COUT * CHW + (mhi - bb * CHW); }
        #pragma unroll
        for (int nt = 0; nt < 8; nt++) {
            const int f0 = wn * 64 + nt * 8 + tg * 2;
            const float b0 = s_bias[f0], b1 = s_bias[f0 + 1];
            if (vlo) {
                plo[(size_t)f0 * CHW]       = acc[mt][nt][0] + b0;
                plo[(size_t)(f0 + 1) * CHW] = acc[mt][nt][1] + b1;
            }
            if (vhi) {
                phi[(size_t)f0 * CHW]       = acc[mt][nt][2] + b0;
                phi[(size_t)(f0 + 1) * CHW] = acc[mt][nt][3] + b1;
            }
        }
    }
    #undef LOAD_CHUNK
}

// ---------------------------------------------------------------------------
// Launch.
// ---------------------------------------------------------------------------
extern "C" void kernel_launch(void* const* d_in, const int* in_sizes, int n_in,
                              void* d_out, int out_size) {
    const float* x      = (const float*)d_in[0];
    const float* qw     = (const float*)d_in[1];
    const float* vals   = (const float*)d_in[2];
    const float* weight = (const float*)d_in[3];
    const float* bias   = (const float*)d_in[4];
    const int*   seg    = (const int*)d_in[5];
    const int*   lat    = (const int*)d_in[6];
    const int*   lon    = (const int*)d_in[7];
    const int    nnz    = in_sizes[2];

    dim3 tgrid((CHW + 31) / 32, CIN / 32, BSZ);
    transpose_kernel<<<tgrid, dim3(32, 8)>>>(x);
    wconv_kernel<<<(COUT * CK + 255) / 256, 256>>>(weight);
    merge_kernel<<<(NLAT * 32 + 127) / 128, 128>>>(seg, lat, lon, vals, qw, nnz);

    dim3 ggrid(NPT, NLAT, BSZ);
    gather_kernel<<<ggrid, 256>>>();

    const int dyn_bytes = NSTG * BUFW * sizeof(float);   // 110592
    cudaFuncSetAttribute(gemm_mma_kernel,
                         cudaFuncAttributeMaxDynamicSharedMemorySize, dyn_bytes);
    gemm_mma_kernel<<<MBLK, 256, dyn_bytes>>>(bias, (float*)d_out);
}

// round 10
// speedup vs baseline: 1.1602x; 1.1467x over previous
#include <cuda_runtime.h>
#include <cuda_fp16.h>
#include <cstdint>

// Problem constants
#define NLAT 181
#define NLON 360
#define CIN  128
#define COUT 128
#define KS   3
#define BSZ  2
#define CHW  (NLAT * NLON)     // 65160
#define CK   (CIN * KS)        // 384
#define PT   32                // gather p-tile
#define NPT  12
#define MTOT  (BSZ * CHW)      // 130320
#define MTILE 128
#define MBLK  ((MTOT + MTILE - 1) / MTILE)   // 1019
#define MPADL (MBLK * MTILE)                 // 130432
#define WSLOT 4096
#define RSLOT 512
#define KCH   32               // GEMM K-chunk (halves)
#define NCH   (CK / KCH)       // 12
#define SROWB 112              // smem row stride bytes (32 halves padded): 16B-aligned, conflict-free
#define CHNKB (128 * SROWB)    // 14336 bytes per matrix per chunk
#define STGB  (2 * CHNKB)      // 28672 bytes per stage (A+B)
#define NSTG  3

// Scratch (device globals — allocation-free; zero-init so padded z rows are 0)
__device__ float  g_xt[(size_t)BSZ * CHW * CIN];   // x transposed: [b][h*w][c]
__device__ float4 g_rw[NLAT * WSLOT];              // run weights {w0,w1,w2,0}
__device__ int4   g_runs[NLAT * RSLOT];            // {la, lo0, cnt_padded, wabs}
__device__ int    g_rcnt[NLAT];
__device__ __half g_zh[(size_t)MPADL * CK];        // z M-major [m][ck], fp16
__device__ __half g_wh[COUT * CK];                 // W [f][ck], fp16

// ---------------- helpers ----------------
__device__ __forceinline__ void fma2(unsigned long long& d,
                                     unsigned long long a,
                                     unsigned long long b) {
    asm("fma.rn.f32x2 %0, %1, %2, %0;" : "+l"(d) : "l"(a), "l"(b));
}
__device__ __forceinline__ unsigned long long pack2(float x, float y) {
    unsigned long long r;
    asm("mov.b64 %0, {%1, %2};" : "=l"(r) : "f"(x), "f"(y));
    return r;
}
union F4U { float4 f; unsigned long long u[2]; };
union U2F { unsigned long long u; float2 f; };

__device__ __forceinline__ uint32_t smem_u32(const void* p) {
    uint32_t a;
    asm("{ .reg .u64 t; cvta.to.shared.u64 t, %1; cvt.u32.u64 %0, t; }"
        : "=r"(a) : "l"(p));
    return a;
}
__device__ __forceinline__ void cpasync16(uint32_t s, const void* g) {
    asm volatile("cp.async.cg.shared.global [%0], [%1], 16;" :: "r"(s), "l"(g));
}
__device__ __forceinline__ void cp_commit() {
    asm volatile("cp.async.commit_group;" ::: "memory");
}
template <int N>
__device__ __forceinline__ void cp_wait() {
    asm volatile("cp.async.wait_group %0;" :: "n"(N) : "memory");
}
__device__ __forceinline__ void mma_f16(float* d, const uint32_t* a,
                                        uint32_t b0, uint32_t b1) {
    asm volatile(
        "mma.sync.aligned.m16n8k16.row.col.f32.f16.f16.f32 "
        "{%0,%1,%2,%3}, {%4,%5,%6,%7}, {%8,%9}, {%0,%1,%2,%3};"
        : "+f"(d[0]), "+f"(d[1]), "+f"(d[2]), "+f"(d[3])
        : "r"(a[0]), "r"(a[1]), "r"(a[2]), "r"(a[3]), "r"(b0), "r"(b1));
}
__device__ __forceinline__ void ldsm_x4(uint32_t& r0, uint32_t& r1,
                                        uint32_t& r2, uint32_t& r3, uint32_t addr) {
    asm volatile("ldmatrix.sync.aligned.m8n8.x4.shared.b16 {%0,%1,%2,%3}, [%4];"
                 : "=r"(r0), "=r"(r1), "=r"(r2), "=r"(r3) : "r"(addr));
}

// ---------------------------------------------------------------------------
// Transpose x[b][c][hw] -> g_xt[b][hw][c]
// ---------------------------------------------------------------------------
__global__ void transpose_kernel(const float* __restrict__ x) {
    __shared__ float tile[32][33];
    const int hw0 = blockIdx.x * 32;
    const int c0  = blockIdx.y * 32;
    const int b   = blockIdx.z;
    const int tx = threadIdx.x, ty = threadIdx.y;
    #pragma unroll
    for (int i = 0; i < 4; i++) {
        int c  = c0 + ty + i * 8;
        int hw = hw0 + tx;
        if (hw < CHW)
            tile[ty + i * 8][tx] = x[((size_t)b * CIN + c) * CHW + hw];
    }
    __syncthreads();
    #pragma unroll
    for (int i = 0; i < 4; i++) {
        int hw = hw0 + ty + i * 8;
        int c  = c0 + tx;
        if (hw < CHW)
            g_xt[((size_t)b * CHW + hw) * CIN + c] = tile[tx][ty + i * 8];
    }
}

// W[f][ck] -> fp16 copy
__global__ void wconv_kernel(const float* __restrict__ w) {
    int i = blockIdx.x * 256 + threadIdx.x;
    if (i < COUT * CK) g_wh[i] = __float2half_rn(w[i]);
}

// ---------------------------------------------------------------------------
// Merge: warp per t. Emits per-(t,la) runs of consecutive lons with
// branch-free weight triples, zero-padded to multiples of 4 entries.
// ---------------------------------------------------------------------------
__global__ void merge_kernel(const int* __restrict__ seg,
                             const int* __restrict__ lat,
                             const int* __restrict__ lon,
                             const float* __restrict__ vals,
                             const float* __restrict__ qw,
                             int nnz) {
    const int t    = (blockIdx.x * blockDim.x + threadIdx.x) >> 5;
    const int lane = threadIdx.x & 31;
    if (t >= NLAT) return;

    int sb[4];
    #pragma unroll
    for (int k = 0; k < 4; k++) {
        const int j = t * KS + k;
        int lo = 0, hi = nnz;
        while (lo < hi) {
            int m = (lo + hi) >> 1;
            int sgv = seg[m];
            int key = (sgv % NLAT) * KS + (sgv / NLAT);
            if (key < j) lo = m + 1; else hi = m;
        }
        sb[k] = lo;
    }

    const int wlim = (t + 1) * WSLOT;
    int wabs = 0, rbase = 0;
    int entc = 0, runsc = 0;

    for (int pass = 0; pass < 2; pass++) {
        int ent = 0, runs = 0;
        for (int la = lane; la < NLAT; la += 32) {
            int bks[3], eks[3];
            #pragma unroll
            for (int k = 0; k < 3; k++) {
                int lo = sb[k], hi = sb[k + 1];
                while (lo < hi) { int m = (lo + hi) >> 1; if (lat[m] < la) lo = m + 1; else hi = m; }
                bks[k] = lo;
                hi = sb[k + 1];
                while (lo < hi) { int m = (lo + hi) >> 1; if (lat[m] < la + 1) lo = m + 1; else hi = m; }
                eks[k] = lo;
            }
            int p0 = bks[0], p1 = bks[1], p2 = bks[2];
            const float q = qw[la];
            int prev = -2, rstart = ent, rcnt = 0, rlo0 = 0;
            while (p0 < eks[0] || p1 < eks[1] || p2 < eks[2]) {
                int l0 = (p0 < eks[0]) ? lon[p0] : 0x7fffffff;
                int l1 = (p1 < eks[1]) ? lon[p1] : 0x7fffffff;
                int l2 = (p2 < eks[2]) ? lon[p2] : 0x7fffffff;
                int lm = min(l0, min(l1, l2));
                float w0 = 0.f, w1 = 0.f, w2 = 0.f;
                if (l0 == lm) { w0 = vals[p0] * q; p0++; }
                if (l1 == lm) { w1 = vals[p1] * q; p1++; }
                if (l2 == lm) { w2 = vals[p2] * q; p2++; }
                if (w0 == 0.f && w1 == 0.f && w2 == 0.f) continue;
                if (rcnt > 0 && lm != prev + 1) {
                    int pad = (4 - (rcnt & 3)) & 3;
                    if (pass == 1) {
                        for (int z = 0; z < pad; z++) {
                            int ai = wabs + rstart + rcnt + z;
                            if (ai < wlim) g_rw[ai] = make_float4(0.f, 0.f, 0.f, 0.f);
                        }
                        int ri = rbase + runs;
                        if (ri < RSLOT)
                            g_runs[t * RSLOT + ri] =
                                make_int4(la, rlo0, rcnt + pad, wabs + rstart);
                    }
                    runs++;
                    ent = rstart + rcnt + pad;
                    rstart = ent; rcnt = 0;
                }
                if (rcnt == 0) rlo0 = lm;
                if (pass == 1) {
                    int ai = wabs + rstart + rcnt;
                    if (ai < wlim) g_rw[ai] = make_float4(w0, w1, w2, 0.f);
                }
                rcnt++;
                ent = rstart + rcnt;
                prev = lm;
            }
            if (rcnt > 0) {
                int pad = (4 - (rcnt & 3)) & 3;
                if (pass == 1) {
                    for (int z = 0; z < pad; z++) {
                        int ai = wabs + rstart + rcnt + z;
                        if (ai < wlim) g_rw[ai] = make_float4(0.f, 0.f, 0.f, 0.f);
                    }
                    int ri = rbase + runs;
                    if (ri < RSLOT)
                        g_runs[t * RSLOT + ri] =
                            make_int4(la, rlo0, rcnt + pad, wabs + rstart);
                }
                runs++;
                ent = rstart + rcnt + pad;
            }
        }
        if (pass == 0) {
            entc = ent; runsc = runs;
            int ei = entc, ri = runsc;
            #pragma unroll
            for (int d = 1; d < 32; d <<= 1) {
                int v = __shfl_up_sync(0xffffffffu, ei, d);
                int u = __shfl_up_sync(0xffffffffu, ri, d);
                if (lane >= d) { ei += v; ri += u; }
            }
            wabs  = t * WSLOT + (ei - entc);
            rbase = ri - runsc;
            if (lane == 31) g_rcnt[t] = min(ri, RSLOT);
        }
    }
}

// ---------------------------------------------------------------------------
// Stage 1: gather with rolling column window. Writes z M-major g_zh[m][ck]
// as fp16 (RN) for the mma stage; accumulation itself stays fp32-exact.
// ---------------------------------------------------------------------------
__global__ void __launch_bounds__(256, 2)
gather_kernel() {
    const int tid  = threadIdx.x;
    const int warp = tid >> 5;
    const int lane = tid & 31;

    const int yb = blockIdx.y;
    const int t  = (yb & 1) ? (NLAT - 1 - (yb >> 1)) : (yb >> 1);   // pole-first
    const int b  = blockIdx.z;
    const int p0 = blockIdx.x * PT;
    const int pbase = p0 + warp * 4;

    const int nruns = g_rcnt[t];
    const int4* runs = g_runs + (size_t)t * RSLOT;
    const float4* xb = (const float4*)(g_xt + (size_t)b * CHW * CIN);

    unsigned long long a2[3][4][2];
    #pragma unroll
    for (int k = 0; k < 3; k++)
        #pragma unroll
        for (int q = 0; q < 4; q++) { a2[k][q][0] = 0ull; a2[k][q][1] = 0ull; }

    for (int r = 0; r < nruns; r++) {
        const int4 rn = __ldg(&runs[r]);
        const int la   = rn.x;
        const int cnt  = rn.z;
        const float4* wp = g_rw + rn.w;
        const int rowb = la * NLON;

        int col = rn.y + pbase;
        if (col >= NLON) col -= NLON;
        if (col >= NLON) col -= NLON;
        int c1 = col + 1; if (c1 >= NLON) c1 -= NLON;
        int c2 = c1 + 1;  if (c2 >= NLON) c2 -= NLON;

        F4U w0v, w1v, w2v;
        w0v.f = xb[(size_t)(rowb + col) * 32 + lane];
        w1v.f = xb[(size_t)(rowb + c1)  * 32 + lane];
        w2v.f = xb[(size_t)(rowb + c2)  * 32 + lane];
        int colx = c2;

        for (int j4 = 0; j4 < cnt; j4 += 4) {
            int n0 = colx + 1; if (n0 >= NLON) n0 -= NLON;
            int n1 = colx + 2; if (n1 >= NLON) n1 -= NLON;
            int n2 = colx + 3; if (n2 >= NLON) n2 -= NLON;
            int n3 = colx + 4; if (n3 >= NLON) n3 -= NLON;
            colx = n3;
            F4U nw0, nw1, nw2, nw3;
            nw0.f = xb[(size_t)(rowb + n0) * 32 + lane];
            nw1.f = xb[(size_t)(rowb + n1) * 32 + lane];
            nw2.f = xb[(size_t)(rowb + n2) * 32 + lane];
            nw3.f = xb[(size_t)(rowb + n3) * 32 + lane];

            float4 wa = __ldg(&wp[j4 + 0]);
            float4 wb = __ldg(&wp[j4 + 1]);
            float4 wc = __ldg(&wp[j4 + 2]);
            float4 wd = __ldg(&wp[j4 + 3]);

            #define DO_ENTRY(W, V0, V1, V2, V3)                                   \
            {                                                                     \
                unsigned long long k0 = pack2(W.x, W.x);                          \
                unsigned long long k1 = pack2(W.y, W.y);                          \
                unsigned long long k2 = pack2(W.z, W.z);                          \
                fma2(a2[0][0][0], k0, V0.u[0]); fma2(a2[0][0][1], k0, V0.u[1]);   \
                fma2(a2[1][0][0], k1, V0.u[0]); fma2(a2[1][0][1], k1, V0.u[1]);   \
                fma2(a2[2][0][0], k2, V0.u[0]); fma2(a2[2][0][1], k2, V0.u[1]);   \
                fma2(a2[0][1][0], k0, V1.u[0]); fma2(a2[0][1][1], k0, V1.u[1]);   \
                fma2(a2[1][1][0], k1, V1.u[0]); fma2(a2[1][1][1], k1, V1.u[1]);   \
                fma2(a2[2][1][0], k2, V1.u[0]); fma2(a2[2][1][1], k2, V1.u[1]);   \
                fma2(a2[0][2][0], k0, V2.u[0]); fma2(a2[0][2][1], k0, V2.u[1]);   \
                fma2(a2[1][2][0], k1, V2.u[0]); fma2(a2[1][2][1], k1, V2.u[1]);   \
                fma2(a2[2][2][0], k2, V2.u[0]); fma2(a2[2][2][1], k2, V2.u[1]);   \
                fma2(a2[0][3][0], k0, V3.u[0]); fma2(a2[0][3][1], k0, V3.u[1]);   \
                fma2(a2[1][3][0], k1, V3.u[0]); fma2(a2[1][3][1], k1, V3.u[1]);   \
                fma2(a2[2][3][0], k2, V3.u[0]); fma2(a2[2][3][1], k2, V3.u[1]);   \
            }
            DO_ENTRY(wa, w0v, w1v, w2v, nw0)
            DO_ENTRY(wb, w1v, w2v, nw0, nw1)
            DO_ENTRY(wc, w2v, nw0, nw1, nw2)
            DO_ENTRY(wd, nw0, nw1, nw2, nw3)
            #undef DO_ENTRY
            w0v = nw1; w1v = nw2; w2v = nw3;
        }
    }

    // store z[m][ck] as fp16: ck = (lane*4 + c)*3 + k, 12 halves per q
    if (pbase < NLON) {
        const size_t mb = (size_t)(b * NLAT + t) * NLON + pbase;
        #pragma unroll
        for (int q = 0; q < 4; q++) {
            __half2* zp = (__half2*)(g_zh + (mb + q) * (size_t)CK + lane * 12);
            U2F c0k0, c0k1, c0k2, c1k0, c1k1, c1k2;
            c0k0.u = a2[0][q][0]; c0k1.u = a2[1][q][0]; c0k2.u = a2[2][q][0];
            c1k0.u = a2[0][q][1]; c1k1.u = a2[1][q][1]; c1k2.u = a2[2][q][1];
            zp[0] = __floats2half2_rn(c0k0.f.x, c0k1.f.x);
            zp[1] = __floats2half2_rn(c0k2.f.x, c0k0.f.y);
            zp[2] = __floats2half2_rn(c0k1.f.y, c0k2.f.y);
            zp[3] = __floats2half2_rn(c1k0.f.x, c1k1.f.x);
            zp[4] = __floats2half2_rn(c1k2.f.x, c1k0.f.y);
            zp[5] = __floats2half2_rn(c1k1.f.y, c1k2.f.y);
        }
    }
}

// ---------------------------------------------------------------------------
// Stage 2: fp16 mma.sync m16n8k16 GEMM, 3-stage cp.async pipeline.
// Per CTA: D[128m x 128f] = z[128m x 384] @ W^T (fp16 in, fp32 accum).
// Per chunk: 2 k-steps of 16; per k-step per warp: 2 A-ldmatrix.x4 +
// 4 B-ldmatrix.x4 + 16 mma.
// ---------------------------------------------------------------------------
__global__ void __launch_bounds__(256, 2)
gemm_mma_kernel(const float* __restrict__ bias, float* __restrict__ out) {
    extern __shared__ __align__(16) char smem[];     // [NSTG][STGB]
    __shared__ float s_bias[COUT];

    const int tid  = threadIdx.x;
    const int warp = tid >> 5;
    const int lane = tid & 31;
    const int g    = lane >> 2;
    const int tg   = lane & 3;
    const int wm   = warp & 3;          // m-warp (4 x 32 rows)
    const int wn   = warp >> 2;         // f-warp (2 x 64 cols)
    const int m0   = blockIdx.x * MTILE;

    const uint32_t sbase = smem_u32(smem);
    const int lrw = tid >> 1;           // load row 0..127
    const int lsg = (tid & 1) * 2;      // 16B segment base (0 or 2)

    if (tid < COUT) s_bias[tid] = __ldg(bias + tid);

    // ldmatrix per-lane base addresses (bytes), before stage/k offsets.
    const uint32_t lrow = (uint32_t)(lane & 15);
    const uint32_t lsel = (uint32_t)(lane >> 4) * 16;
    uint32_t a_adr[2], b_adr[4];
    #pragma unroll
    for (int mt = 0; mt < 2; mt++)
        a_adr[mt] = sbase + (wm * 32 + mt * 16 + lrow) * SROWB + lsel;
    #pragma unroll
    for (int pr = 0; pr < 4; pr++)
        b_adr[pr] = sbase + CHNKB + (wn * 64 + pr * 16 + lrow) * SROWB + lsel;

    float acc[2][8][4];
    #pragma unroll
    for (int mt = 0; mt < 2; mt++)
        #pragma unroll
        for (int nt = 0; nt < 8; nt++)
            #pragma unroll
            for (int i = 0; i < 4; i++) acc[mt][nt][i] = 0.f;

    #define LOAD_CHUNK(CH, BUFI)                                                   \
    {                                                                              \
        const uint32_t sa = sbase + (uint32_t)(BUFI) * STGB;                       \
        _Pragma("unroll")                                                          \
        for (int s = 0; s < 2; s++) {                                              \
            const int seg = lsg + s;                                               \
            const uint32_t so = (uint32_t)(lrw * SROWB + seg * 16);                \
            cpasync16(sa + so, &g_zh[(size_t)(m0 + lrw) * CK + (CH) * KCH + seg * 8]); \
            cpasync16(sa + CHNKB + so, &g_wh[lrw * CK + (CH) * KCH + seg * 8]);    \
        }                                                                          \
        cp_commit();                                                               \
    }

    LOAD_CHUNK(0, 0)
    LOAD_CHUNK(1, 1)

    for (int ch = 0; ch < NCH; ch++) {
        if (ch + 1 < NCH) cp_wait<1>(); else cp_wait<0>();
        __syncthreads();
        if (ch + 2 < NCH) { LOAD_CHUNK(ch + 2, (ch + 2) % NSTG) }

        const uint32_t bufo = (uint32_t)(ch % NSTG) * STGB;
        #pragma unroll
        for (int ksk = 0; ksk < 2; ksk++) {
            const uint32_t ko = bufo + ksk * 32;   // 16 halves = 32 bytes
            uint32_t afr[2][4];
            #pragma unroll
            for (int mt = 0; mt < 2; mt++)
                ldsm_x4(afr[mt][0], afr[mt][1], afr[mt][2], afr[mt][3],
                        a_adr[mt] + ko);
            #pragma unroll
            for (int pr = 0; pr < 4; pr++) {
                uint32_t r0, r1, r2, r3;   // (noct0,klo)(noct1,klo)(noct0,khi)(noct1,khi)
                ldsm_x4(r0, r1, r2, r3, b_adr[pr] + ko);
                mma_f16(acc[0][2 * pr],     afr[0], r0, r2);
                mma_f16(acc[1][2 * pr],     afr[1], r0, r2);
                mma_f16(acc[0][2 * pr + 1], afr[0], r1, r3);
                mma_f16(acc[1][2 * pr + 1], afr[1], r1, r3);
            }
        }
    }

    // Epilogue: D[m][f] -> out[b][f][t][p] with bias.
    #pragma unroll
    for (int mt = 0; mt < 2; mt++) {
        const int mlo = m0 + wm * 32 + mt * 16 + g;
        const int mhi = mlo + 8;
        const bool vlo = (mlo < MTOT), vhi = (mhi < MTOT);
        float* plo = nullptr;
        float* phi = nullptr;
        if (vlo) { int bb = mlo / CHW; plo = out + (size_t)bb * COUT * CHW + (mlo - bb * CHW); }
        if (vhi) { int bb = mhi / CHW; phi = out + (size_t)bb * COUT * CHW + (mhi - bb * CHW); }
        #pragma unroll
        for (int nt = 0; nt < 8; nt++) {
            const int f0 = wn * 64 + nt * 8 + tg * 2;
            const float b0 = s_bias[f0], b1 = s_bias[f0 + 1];
            if (vlo) {
                plo[(size_t)f0 * CHW]       = acc[mt][nt][0] + b0;
                plo[(size_t)(f0 + 1) * CHW] = acc[mt][nt][1] + b1;
            }
            if (vhi) {
                phi[(size_t)f0 * CHW]       = acc[mt][nt][2] + b0;
                phi[(size_t)(f0 + 1) * CHW] = acc[mt][nt][3] + b1;
            }
        }
    }
    #undef LOAD_CHUNK
}

// ---------------------------------------------------------------------------
// Launch.
// ---------------------------------------------------------------------------
extern "C" void kernel_launch(void* const* d_in, const int* in_sizes, int n_in,
                              void* d_out, int out_size) {
    const float* x      = (const float*)d_in[0];
    const float* qw     = (const float*)d_in[1];
    const float* vals   = (const float*)d_in[2];
    const float* weight = (const float*)d_in[3];
    const float* bias   = (const float*)d_in[4];
    const int*   seg    = (const int*)d_in[5];
    const int*   lat    = (const int*)d_in[6];
    const int*   lon    = (const int*)d_in[7];
    const int    nnz    = in_sizes[2];

    dim3 tgrid((CHW + 31) / 32, CIN / 32, BSZ);
    transpose_kernel<<<tgrid, dim3(32, 8)>>>(x);
    wconv_kernel<<<(COUT * CK + 255) / 256, 256>>>(weight);
    merge_kernel<<<(NLAT * 32 + 127) / 128, 128>>>(seg, lat, lon, vals, qw, nnz);

    dim3 ggrid(NPT, NLAT, BSZ);
    gather_kernel<<<ggrid, 256>>>();

    const int dyn_bytes = NSTG * STGB;   // 86016
    cudaFuncSetAttribute(gemm_mma_kernel,
                         cudaFuncAttributeMaxDynamicSharedMemorySize, dyn_bytes);
    gemm_mma_kernel<<<MBLK, 256, dyn_bytes>>>(bias, (float*)d_out);
}